// round 1
// baseline (speedup 1.0000x reference)
#include <cuda_runtime.h>
#include <math.h>

#define BB 128
#define LL 31
#define TT 32
#define EE 512
#define TAGN 512
#define KIN 1024        // E + TAG
#define HH 1024
#define G4 4096         // 4*H
#define VV 30000
#define KSPLIT 4
#define KCH (HH / KSPLIT)   // 256

// ---- scratch (device globals; no allocation allowed) ----
__device__ float d_gx[(size_t)BB * TT * G4];        // 64 MB: [b*32+t][4H]
__device__ float d_part[KSPLIT][(size_t)BB * G4];   // 8 MB: split-K partials
__device__ float d_h[(size_t)TT * BB * HH];         // 16 MB: [t][b][H]
__device__ float d_c[(size_t)BB * HH];              // cell state
__device__ float d_zero[(size_t)BB * HH];           // never written -> stays 0
__device__ int   d_rowmap[BB * TT];                 // packed row -> t*128+b

// ------------------------------------------------------------------
// meta: rowmap for pack_padded_sequence semantics of the reference.
// n_t = count(lengths > t); packed rows at time t are batches 0..n_t-1
// (original ascending-length order, exactly like the reference slicing).
// ------------------------------------------------------------------
__global__ void meta_kernel(const int* __restrict__ lengths) {
    __shared__ int len[BB];
    __shared__ int nt[TT];
    __shared__ int off[TT];
    int tid = threadIdx.x;
    len[tid] = lengths[tid];
    __syncthreads();
    if (tid < TT) {
        int c = 0;
        for (int b = 0; b < BB; b++) c += (len[b] > tid) ? 1 : 0;
        nt[tid] = c;
    }
    __syncthreads();
    if (tid == 0) {
        int s = 0;
        for (int t = 0; t < TT; t++) { off[t] = s; s += nt[t]; }
    }
    __syncthreads();
    for (int t = 0; t < TT; t++) {
        int n = nt[t], o = off[t];
        for (int b = tid; b < n; b += blockDim.x)
            d_rowmap[o + b] = t * BB + b;
    }
}

// ------------------------------------------------------------------
// gx = xt @ W_ih^T + b_ih + b_hh, with xt gathered on the fly:
//   k <  512: t==0 ? features[b] : W_embed[captions[b][t-1]]
//   k >= 512: tags[b]
// M=4096 (rows b*32+t), N=4096, K=1024. 128x128 tile, 8x8 microtile.
// ------------------------------------------------------------------
__global__ __launch_bounds__(256) void gx_kernel(
    const float* __restrict__ features, const float* __restrict__ tags,
    const int* __restrict__ captions, const float* __restrict__ W_embed,
    const float* __restrict__ W_ih, const float* __restrict__ b_ih,
    const float* __restrict__ b_hh)
{
    __shared__ float As[8][128];
    __shared__ float Bs[8][128];
    __shared__ const float* rowp[128];
    __shared__ float bias_s[128];

    int tid = threadIdx.x;
    int m0 = blockIdx.y * 128;
    int n0 = blockIdx.x * 128;

    if (tid < 128) {
        int r = m0 + tid;
        int b = r >> 5, t = r & 31;
        rowp[tid] = (t == 0) ? (features + (size_t)b * EE)
                             : (W_embed + (size_t)captions[b * LL + (t - 1)] * EE);
        bias_s[tid] = b_ih[n0 + tid] + b_hh[n0 + tid];
    }
    __syncthreads();

    int lr = tid >> 1;           // tile row for loads (0..127)
    int lk = (tid & 1) * 4;      // k sub-offset (0 or 4)
    int bA = (m0 + lr) >> 5;
    const float* tagbase = tags + (size_t)bA * TAGN;
    const float* wb = W_ih + (size_t)(n0 + lr) * KIN + lk;

    int ty = tid >> 4, tx = tid & 15;
    int ms = ty * 8, ns = tx * 8;

    float acc[8][8];
    #pragma unroll
    for (int i = 0; i < 8; i++)
        #pragma unroll
        for (int j = 0; j < 8; j++) acc[i][j] = 0.f;

    float4 pa = *reinterpret_cast<const float4*>(rowp[lr] + lk);
    float4 pb = *reinterpret_cast<const float4*>(wb);

    for (int k0 = 0; k0 < KIN; k0 += 8) {
        __syncthreads();
        As[lk + 0][lr] = pa.x; As[lk + 1][lr] = pa.y;
        As[lk + 2][lr] = pa.z; As[lk + 3][lr] = pa.w;
        Bs[lk + 0][lr] = pb.x; Bs[lk + 1][lr] = pb.y;
        Bs[lk + 2][lr] = pb.z; Bs[lk + 3][lr] = pb.w;
        __syncthreads();
        int kn = k0 + 8;
        if (kn < KIN) {
            int k = kn + lk;
            pa = (k < EE) ? *reinterpret_cast<const float4*>(rowp[lr] + k)
                          : *reinterpret_cast<const float4*>(tagbase + (k - EE));
            pb = *reinterpret_cast<const float4*>(wb + kn);
        }
        #pragma unroll
        for (int kk = 0; kk < 8; kk++) {
            float a[8], bv[8];
            *reinterpret_cast<float4*>(&a[0])  = *reinterpret_cast<const float4*>(&As[kk][ms]);
            *reinterpret_cast<float4*>(&a[4])  = *reinterpret_cast<const float4*>(&As[kk][ms + 4]);
            *reinterpret_cast<float4*>(&bv[0]) = *reinterpret_cast<const float4*>(&Bs[kk][ns]);
            *reinterpret_cast<float4*>(&bv[4]) = *reinterpret_cast<const float4*>(&Bs[kk][ns + 4]);
            #pragma unroll
            for (int i = 0; i < 8; i++)
                #pragma unroll
                for (int j = 0; j < 8; j++)
                    acc[i][j] += a[i] * bv[j];
        }
    }

    #pragma unroll
    for (int i = 0; i < 8; i++) {
        size_t row = (size_t)(m0 + ms + i) * G4 + n0;
        #pragma unroll
        for (int j = 0; j < 8; j += 4) {
            float4 v;
            v.x = acc[i][j]     + bias_s[ns + j];
            v.y = acc[i][j + 1] + bias_s[ns + j + 1];
            v.z = acc[i][j + 2] + bias_s[ns + j + 2];
            v.w = acc[i][j + 3] + bias_s[ns + j + 3];
            *reinterpret_cast<float4*>(&d_gx[row + ns + j]) = v;
        }
    }
}

// ------------------------------------------------------------------
// per-step recurrent GEMM, split-K (4 chunks of 256) for occupancy:
//   part[ks][b][g] = sum_{j in chunk ks} h_prev[b][j] * W_hh[g][j]
// grid (32 n-tiles, 4 k-splits) = 128 blocks.
// ------------------------------------------------------------------
__global__ __launch_bounds__(256) void step_gemm(int t, const float* __restrict__ W_hh)
{
    __shared__ float As[8][128];
    __shared__ float Bs[8][128];
    int tid = threadIdx.x;
    int n0 = blockIdx.x * 128;
    int kbase = blockIdx.y * KCH;

    const float* hprev = (t == 0) ? d_zero : (d_h + (size_t)(t - 1) * BB * HH);

    int lr = tid >> 1;
    int lk = (tid & 1) * 4;
    const float* ha = hprev + (size_t)lr * HH + kbase + lk;
    const float* wb = W_hh + (size_t)(n0 + lr) * HH + kbase + lk;

    int ty = tid >> 4, tx = tid & 15;
    int ms = ty * 8, ns = tx * 8;

    float acc[8][8];
    #pragma unroll
    for (int i = 0; i < 8; i++)
        #pragma unroll
        for (int j = 0; j < 8; j++) acc[i][j] = 0.f;

    float4 pa = *reinterpret_cast<const float4*>(ha);
    float4 pb = *reinterpret_cast<const float4*>(wb);

    for (int k0 = 0; k0 < KCH; k0 += 8) {
        __syncthreads();
        As[lk + 0][lr] = pa.x; As[lk + 1][lr] = pa.y;
        As[lk + 2][lr] = pa.z; As[lk + 3][lr] = pa.w;
        Bs[lk + 0][lr] = pb.x; Bs[lk + 1][lr] = pb.y;
        Bs[lk + 2][lr] = pb.z; Bs[lk + 3][lr] = pb.w;
        __syncthreads();
        if (k0 + 8 < KCH) {
            pa = *reinterpret_cast<const float4*>(ha + k0 + 8);
            pb = *reinterpret_cast<const float4*>(wb + k0 + 8);
        }
        #pragma unroll
        for (int kk = 0; kk < 8; kk++) {
            float a[8], bv[8];
            *reinterpret_cast<float4*>(&a[0])  = *reinterpret_cast<const float4*>(&As[kk][ms]);
            *reinterpret_cast<float4*>(&a[4])  = *reinterpret_cast<const float4*>(&As[kk][ms + 4]);
            *reinterpret_cast<float4*>(&bv[0]) = *reinterpret_cast<const float4*>(&Bs[kk][ns]);
            *reinterpret_cast<float4*>(&bv[4]) = *reinterpret_cast<const float4*>(&Bs[kk][ns + 4]);
            #pragma unroll
            for (int i = 0; i < 8; i++)
                #pragma unroll
                for (int j = 0; j < 8; j++)
                    acc[i][j] += a[i] * bv[j];
        }
    }

    float* dst = d_part[blockIdx.y];
    #pragma unroll
    for (int i = 0; i < 8; i++) {
        size_t row = (size_t)(ms + i) * G4 + n0;
        #pragma unroll
        for (int j = 0; j < 8; j += 4) {
            float4 v;
            v.x = acc[i][j]; v.y = acc[i][j + 1]; v.z = acc[i][j + 2]; v.w = acc[i][j + 3];
            *reinterpret_cast<float4*>(&dst[row + ns + j]) = v;
        }
    }
}

// ------------------------------------------------------------------
// per-step LSTM elementwise: combine gx + 4 split-K partials,
// gate order i,f,g,o (PyTorch), update c, write h[t].
// ------------------------------------------------------------------
__global__ void lstm_ew(int t)
{
    int idx = blockIdx.x * blockDim.x + threadIdx.x;
    if (idx >= BB * HH) return;
    int b = idx >> 10;          // H = 1024
    int j = idx & (HH - 1);
    size_t gxrow = (size_t)(b * TT + t) * G4;
    size_t prow  = (size_t)b * G4;

    float gi = d_gx[gxrow + j];
    float gf = d_gx[gxrow + HH + j];
    float gg = d_gx[gxrow + 2 * HH + j];
    float go = d_gx[gxrow + 3 * HH + j];
    #pragma unroll
    for (int ks = 0; ks < KSPLIT; ks++) {
        gi += d_part[ks][prow + j];
        gf += d_part[ks][prow + HH + j];
        gg += d_part[ks][prow + 2 * HH + j];
        go += d_part[ks][prow + 3 * HH + j];
    }
    float i_ = 1.f / (1.f + expf(-gi));
    float f_ = 1.f / (1.f + expf(-gf));
    float g_ = tanhf(gg);
    float o_ = 1.f / (1.f + expf(-go));
    float cp = (t == 0) ? 0.f : d_c[idx];
    float c  = f_ * cp + i_ * g_;
    d_c[idx] = c;
    d_h[(size_t)t * BB * HH + idx] = o_ * tanhf(c);
}

// ------------------------------------------------------------------
// vocab projection: out[m][v] = h[rowmap[m]] . W_lin[v] + b_lin[v]
// M=N (<=4096), N=30000, K=1024. 128x128 tile, 8x8 microtile.
// ------------------------------------------------------------------
__global__ __launch_bounds__(256) void out_kernel(
    const float* __restrict__ W_lin, const float* __restrict__ b_lin,
    float* __restrict__ out, int N)
{
    __shared__ float As[8][128];
    __shared__ float Bs[8][128];
    __shared__ int rowoff[128];
    __shared__ float bias_s[128];

    int tid = threadIdx.x;
    int m0 = blockIdx.y * 128;
    int n0 = blockIdx.x * 128;

    if (tid < 128) {
        int m = m0 + tid;
        rowoff[tid] = (m < N) ? d_rowmap[m] * HH : 0;
        int v = n0 + tid;
        bias_s[tid] = (v < VV) ? b_lin[v] : 0.f;
    }
    __syncthreads();

    int lr = tid >> 1;
    int lk = (tid & 1) * 4;
    const float* ha = d_h + (size_t)rowoff[lr] + lk;
    int vrow = n0 + lr; if (vrow >= VV) vrow = VV - 1;
    const float* wb = W_lin + (size_t)vrow * HH + lk;

    int ty = tid >> 4, tx = tid & 15;
    int ms = ty * 8, ns = tx * 8;

    float acc[8][8];
    #pragma unroll
    for (int i = 0; i < 8; i++)
        #pragma unroll
        for (int j = 0; j < 8; j++) acc[i][j] = 0.f;

    float4 pa = *reinterpret_cast<const float4*>(ha);
    float4 pb = *reinterpret_cast<const float4*>(wb);

    for (int k0 = 0; k0 < HH; k0 += 8) {
        __syncthreads();
        As[lk + 0][lr] = pa.x; As[lk + 1][lr] = pa.y;
        As[lk + 2][lr] = pa.z; As[lk + 3][lr] = pa.w;
        Bs[lk + 0][lr] = pb.x; Bs[lk + 1][lr] = pb.y;
        Bs[lk + 2][lr] = pb.z; Bs[lk + 3][lr] = pb.w;
        __syncthreads();
        if (k0 + 8 < HH) {
            pa = *reinterpret_cast<const float4*>(ha + k0 + 8);
            pb = *reinterpret_cast<const float4*>(wb + k0 + 8);
        }
        #pragma unroll
        for (int kk = 0; kk < 8; kk++) {
            float a[8], bv[8];
            *reinterpret_cast<float4*>(&a[0])  = *reinterpret_cast<const float4*>(&As[kk][ms]);
            *reinterpret_cast<float4*>(&a[4])  = *reinterpret_cast<const float4*>(&As[kk][ms + 4]);
            *reinterpret_cast<float4*>(&bv[0]) = *reinterpret_cast<const float4*>(&Bs[kk][ns]);
            *reinterpret_cast<float4*>(&bv[4]) = *reinterpret_cast<const float4*>(&Bs[kk][ns + 4]);
            #pragma unroll
            for (int i = 0; i < 8; i++)
                #pragma unroll
                for (int j = 0; j < 8; j++)
                    acc[i][j] += a[i] * bv[j];
        }
    }

    #pragma unroll
    for (int i = 0; i < 8; i++) {
        int m = m0 + ms + i;
        if (m >= N) continue;
        size_t row = (size_t)m * VV;
        #pragma unroll
        for (int j = 0; j < 8; j += 4) {
            int v = n0 + ns + j;
            if (v >= VV) continue;
            float4 q;
            q.x = acc[i][j]     + bias_s[ns + j];
            q.y = acc[i][j + 1] + bias_s[ns + j + 1];
            q.z = acc[i][j + 2] + bias_s[ns + j + 2];
            q.w = acc[i][j + 3] + bias_s[ns + j + 3];
            *reinterpret_cast<float4*>(&out[row + v]) = q;
        }
    }
}

// ------------------------------------------------------------------
extern "C" void kernel_launch(void* const* d_in, const int* in_sizes, int n_in,
                              void* d_out, int out_size) {
    const float* features = (const float*)d_in[0];
    const float* tags     = (const float*)d_in[1];
    const int*   captions = (const int*)d_in[2];
    const int*   lengths  = (const int*)d_in[3];
    const float* W_embed  = (const float*)d_in[4];
    const float* W_ih     = (const float*)d_in[5];
    const float* W_hh     = (const float*)d_in[6];
    const float* b_ih     = (const float*)d_in[7];
    const float* b_hh     = (const float*)d_in[8];
    const float* W_lin    = (const float*)d_in[9];
    const float* b_lin    = (const float*)d_in[10];
    float* out = (float*)d_out;

    int N = out_size / VV;   // sum(lengths)

    meta_kernel<<<1, 128>>>(lengths);
    gx_kernel<<<dim3(32, 32), 256>>>(features, tags, captions, W_embed, W_ih, b_ih, b_hh);
    for (int t = 0; t < TT; t++) {
        step_gemm<<<dim3(32, KSPLIT), 256>>>(t, W_hh);
        lstm_ew<<<(BB * HH + 255) / 256, 256>>>(t);
    }
    out_kernel<<<dim3((VV + 127) / 128, (N + 127) / 128), 256>>>(W_lin, b_lin, out, N);
}

// round 3
// speedup vs baseline: 2.9583x; 2.9583x over previous
#include <cuda_runtime.h>
#include <cuda_fp16.h>
#include <math.h>
#include <stdint.h>

#define BB 128
#define LL 31
#define TT 32
#define EE 512
#define TAGN 512
#define HH 1024
#define G4 4096
#define VV 30000

typedef __half h16;

// ---------------- device scratch ----------------
__device__ __align__(256) float d_gx[(size_t)4096 * 4096];   // [b*32+t][4H]
__device__ __align__(256) float d_part[4][(size_t)BB * G4];  // split-K partials
__device__ __align__(256) float d_c[BB * HH];
__device__ __align__(256) h16 d_hfh[(size_t)4096 * 1024];    // h hi, rows t*128+b
__device__ __align__(256) h16 d_hfl[(size_t)4096 * 1024];    // h lo
__device__ __align__(256) h16 d_xh[(size_t)4096 * 1024];     // xt hi, rows b*32+t
__device__ __align__(256) h16 d_xl[(size_t)4096 * 1024];
__device__ __align__(256) h16 d_Wlf[(size_t)VV * 1024];      // W_lin fp16 (single)
__device__ __align__(256) h16 d_Wih_h[(size_t)4096 * 1024];
__device__ __align__(256) h16 d_Wih_l[(size_t)4096 * 1024];
__device__ __align__(256) h16 d_Whh_h[(size_t)4096 * 1024];
__device__ __align__(256) h16 d_Whh_l[(size_t)4096 * 1024];
__device__ __align__(256) h16 d_zh[BB * 1024];               // never written -> 0
__device__ __align__(256) float d_bias2[G4];
__device__ int d_rowmap[4096];

// ---------------- asm helpers (all portable to plain sm_103) ----------------
__device__ __forceinline__ uint32_t smem_u32(const void* p) {
    uint32_t a;
    asm("{ .reg .u64 t; cvta.to.shared.u64 t, %1; cvt.u32.u64 %0, t; }" : "=r"(a) : "l"(p));
    return a;
}
#define CP16(dst, src) asm volatile("cp.async.cg.shared.global [%0], [%1], 16;" :: "r"(dst), "l"(src))
#define CP_COMMIT()    asm volatile("cp.async.commit_group;")
#define CP_WAIT1()     asm volatile("cp.async.wait_group 1;")
#define CP_WAIT0()     asm volatile("cp.async.wait_group 0;")

__device__ __forceinline__ void ldsm4(uint32_t addr, uint32_t* r) {
    asm volatile("ldmatrix.sync.aligned.m8n8.x4.shared.b16 {%0,%1,%2,%3}, [%4];"
                 : "=r"(r[0]), "=r"(r[1]), "=r"(r[2]), "=r"(r[3]) : "r"(addr));
}
__device__ __forceinline__ void mma16816(float* d, const uint32_t* a, uint32_t b0, uint32_t b1) {
    asm volatile(
        "mma.sync.aligned.m16n8k16.row.col.f32.f16.f16.f32 "
        "{%0,%1,%2,%3}, {%4,%5,%6,%7}, {%8,%9}, {%0,%1,%2,%3};"
        : "+f"(d[0]), "+f"(d[1]), "+f"(d[2]), "+f"(d[3])
        : "r"(a[0]), "r"(a[1]), "r"(a[2]), "r"(a[3]), "r"(b0), "r"(b1));
}

// ---------------- small kernels ----------------
__global__ void meta_kernel(const int* __restrict__ lengths) {
    __shared__ int len[BB];
    __shared__ int nt[TT];
    __shared__ int off[TT];
    int tid = threadIdx.x;
    len[tid] = lengths[tid];
    __syncthreads();
    if (tid < TT) {
        int c = 0;
        for (int b = 0; b < BB; b++) c += (len[b] > tid) ? 1 : 0;
        nt[tid] = c;
    }
    __syncthreads();
    if (tid == 0) {
        int s = 0;
        for (int t = 0; t < TT; t++) { off[t] = s; s += nt[t]; }
    }
    __syncthreads();
    for (int t = 0; t < TT; t++) {
        int n = nt[t], o = off[t];
        for (int b = tid; b < n; b += blockDim.x)
            d_rowmap[o + b] = t * BB + b;
    }
}

// fp32 -> fp16 hi/lo split
__global__ void conv_split(const float* __restrict__ s, h16* __restrict__ hi,
                           h16* __restrict__ lo, int n4) {
    int i = blockIdx.x * blockDim.x + threadIdx.x;
    if (i >= n4) return;
    float4 v = reinterpret_cast<const float4*>(s)[i];
    float vv[4] = {v.x, v.y, v.z, v.w};
    h16 hh[4], ll[4];
#pragma unroll
    for (int j = 0; j < 4; j++) {
        hh[j] = __float2half(vv[j]);
        ll[j] = __float2half(vv[j] - __half2float(hh[j]));
    }
    reinterpret_cast<uint2*>(hi)[i] = *reinterpret_cast<uint2*>(hh);
    reinterpret_cast<uint2*>(lo)[i] = *reinterpret_cast<uint2*>(ll);
}

// fp32 -> fp16 round (single)
__global__ void conv_round(const float* __restrict__ s, h16* __restrict__ o, int n4) {
    int i = blockIdx.x * blockDim.x + threadIdx.x;
    if (i >= n4) return;
    float4 v = reinterpret_cast<const float4*>(s)[i];
    h16 hh[4] = {__float2half(v.x), __float2half(v.y), __float2half(v.z), __float2half(v.w)};
    reinterpret_cast<uint2*>(o)[i] = *reinterpret_cast<uint2*>(hh);
}

__global__ void bias2_k(const float* __restrict__ b_ih, const float* __restrict__ b_hh) {
    int i = blockIdx.x * blockDim.x + threadIdx.x;
    if (i < G4) d_bias2[i] = b_ih[i] + b_hh[i];
}

// gather xt rows (features/embeddings + tags), split fp16 hi/lo
__global__ void conv_xt(const float* __restrict__ features, const float* __restrict__ tags,
                        const int* __restrict__ captions, const float* __restrict__ W_embed) {
    int r = blockIdx.x;            // b*32+t
    int b = r >> 5, t = r & 31;
    int k = threadIdx.x * 4;
    const float* src;
    int kk = k;
    if (k < EE) {
        src = (t == 0) ? (features + (size_t)b * EE)
                       : (W_embed + (size_t)captions[b * LL + (t - 1)] * EE);
    } else {
        src = tags + (size_t)b * TAGN;
        kk = k - EE;
    }
    float4 v = *reinterpret_cast<const float4*>(src + kk);
    float vv[4] = {v.x, v.y, v.z, v.w};
    h16 hh[4], ll[4];
#pragma unroll
    for (int j = 0; j < 4; j++) {
        hh[j] = __float2half(vv[j]);
        ll[j] = __float2half(vv[j] - __half2float(hh[j]));
    }
    size_t o = ((size_t)r * 1024 + k) >> 2;
    reinterpret_cast<uint2*>(d_xh)[o] = *reinterpret_cast<uint2*>(hh);
    reinterpret_cast<uint2*>(d_xl)[o] = *reinterpret_cast<uint2*>(ll);
}

// LSTM elementwise: gates = gx + sum(4 partials); write h as fp16 hi/lo
__global__ void lstm_ew(int t) {
    int idx = blockIdx.x * blockDim.x + threadIdx.x;
    int b = idx >> 10, j = idx & 1023;
    size_t gxr = (size_t)(b * TT + t) * G4 + j;
    size_t gr = (size_t)b * G4 + j;
    float gi = d_gx[gxr], gf = d_gx[gxr + 1024], gg = d_gx[gxr + 2048], go = d_gx[gxr + 3072];
#pragma unroll
    for (int s = 0; s < 4; s++) {
        gi += d_part[s][gr];
        gf += d_part[s][gr + 1024];
        gg += d_part[s][gr + 2048];
        go += d_part[s][gr + 3072];
    }
    float i_ = 1.f / (1.f + expf(-gi));
    float f_ = 1.f / (1.f + expf(-gf));
    float g_ = tanhf(gg);
    float o_ = 1.f / (1.f + expf(-go));
    float c = i_ * g_ + (t ? f_ * d_c[idx] : 0.f);
    d_c[idx] = c;
    float h = o_ * tanhf(c);
    size_t hr = (size_t)(t * BB + b) * 1024 + j;
    h16 hh = __float2half(h);
    d_hfh[hr] = hh;
    d_hfl[hr] = __float2half(h - __half2float(hh));
}

// ---------------- HMMA GEMM ----------------
// out[m][n] (+bias[n]) = sum_seg sum_k Aseg[arow[m]][k] * Bseg[n][k]
// Segments hi/lo fp16; K=1024 per segment in chunks of 64 (128B SW128-swizzled
// rows). BM=BN=128, 8 warps 2x4, warp tile 64x32, 3-stage cp.async pipeline.
// blockIdx.z: split-K over chunk list, writes out + z*zstride.
__global__ __launch_bounds__(256) void gemm_f16(
    const h16* __restrict__ A0, const h16* __restrict__ A1, const h16* __restrict__ A2,
    const h16* __restrict__ B0, const h16* __restrict__ B1, const h16* __restrict__ B2,
    const int* __restrict__ map, const float* __restrict__ bias,
    float* __restrict__ out, int M, int Ndim, int cpz, size_t zstride)
{
    extern __shared__ char sm[];
    int* arow = reinterpret_cast<int*>(sm);
    uint32_t smu = smem_u32(sm);
    const uint32_t aA = smu + 1024;
    const uint32_t aB = aA + 3 * 16384;
    h16* smA = reinterpret_cast<h16*>(sm + 1024);
    h16* smB = reinterpret_cast<h16*>(sm + 1024 + 3 * 16384);

    int tid = threadIdx.x;
    int lane = tid & 31;
    int w = tid >> 5;
    int wm = w >> 2, wn = w & 3;      // 2 x 4 warp grid
    int n0 = blockIdx.x * 128;
    int m0 = blockIdx.y * 128;
    int c0 = blockIdx.z * cpz;
    int c1 = c0 + cpz;
    out += (size_t)blockIdx.z * zstride;

    if (tid < 128) {
        int mm = m0 + tid;
        if (mm >= M) mm = M - 1;
        arow[tid] = map ? map[mm] : mm;
    }
    __syncthreads();

    // ---- async load of one chunk into stage ----
    auto load_chunk = [&](int chunk, int stage) {
        int seg = chunk >> 4;
        int kc = (chunk & 15) * 64;
        const h16* Ap = (seg == 0) ? A0 : (seg == 1) ? A1 : A2;
        const h16* Bp = (seg == 0) ? B0 : (seg == 1) ? B1 : B2;
        uint32_t da = aA + stage * 16384;
        uint32_t db = aB + stage * 16384;
#pragma unroll
        for (int q = 0; q < 4; q++) {
            int idx = q * 256 + tid;
            int row = idx >> 3, c = idx & 7;
            const h16* src = Ap + (size_t)arow[row] * 1024 + kc + c * 8;
            CP16(da + row * 128 + ((c ^ (row & 7)) * 16), src);
        }
#pragma unroll
        for (int q = 0; q < 4; q++) {
            int idx = q * 256 + tid;
            int row = idx >> 3, c = idx & 7;
            int vr = n0 + row;
            if (vr >= Ndim) vr = Ndim - 1;
            const h16* src = Bp + (size_t)vr * 1024 + kc + c * 8;
            CP16(db + row * 128 + ((c ^ (row & 7)) * 16), src);
        }
        CP_COMMIT();
    };

    float acc[4][4][4];
#pragma unroll
    for (int i = 0; i < 4; i++)
#pragma unroll
        for (int j = 0; j < 4; j++)
#pragma unroll
            for (int k = 0; k < 4; k++) acc[i][j][k] = 0.f;

    load_chunk(c0, 0);
    if (c0 + 1 < c1) load_chunk(c0 + 1, 1);

    int lrow = lane & 15;
    int lcol = lane >> 4;

    for (int i = c0; i < c1; i++) {
        if (i + 1 < c1) { CP_WAIT1(); } else { CP_WAIT0(); }
        __syncthreads();
        if (i + 2 < c1) load_chunk(i + 2, (i + 2 - c0) % 3);

        int stage = (i - c0) % 3;
        uint32_t ab = aA + stage * 16384;
        uint32_t bb = aB + stage * 16384;
#pragma unroll
        for (int k16 = 0; k16 < 4; k16++) {
            uint32_t af[4][4];
#pragma unroll
            for (int mt = 0; mt < 4; mt++) {
                int r = wm * 64 + mt * 16 + lrow;
                int c = (k16 * 2 + lcol) ^ (r & 7);
                ldsm4(ab + r * 128 + c * 16, af[mt]);
            }
            uint32_t bf[2][4];
#pragma unroll
            for (int bt = 0; bt < 2; bt++) {
                int r = wn * 32 + bt * 16 + lrow;
                int c = (k16 * 2 + lcol) ^ (r & 7);
                ldsm4(bb + r * 128 + c * 16, bf[bt]);
            }
#pragma unroll
            for (int mt = 0; mt < 4; mt++)
#pragma unroll
                for (int bt = 0; bt < 2; bt++) {
                    mma16816(acc[mt][bt * 2],     af[mt], bf[bt][0], bf[bt][2]);
                    mma16816(acc[mt][bt * 2 + 1], af[mt], bf[bt][1], bf[bt][3]);
                }
        }
        __syncthreads();
    }

    // ---- epilogue ----
    int gr = lane >> 2;
    int gc = (lane & 3) * 2;
#pragma unroll
    for (int mt = 0; mt < 4; mt++) {
        int r0 = m0 + wm * 64 + mt * 16 + gr;
        int r1 = r0 + 8;
#pragma unroll
        for (int j = 0; j < 4; j++) {
            int n = n0 + wn * 32 + j * 8 + gc;
            if (n >= Ndim) continue;
            float bx = 0.f, by = 0.f;
            if (bias) { float2 bv = *reinterpret_cast<const float2*>(bias + n); bx = bv.x; by = bv.y; }
            if (r0 < M) {
                float2 v = make_float2(acc[mt][j][0] + bx, acc[mt][j][1] + by);
                *reinterpret_cast<float2*>(out + (size_t)r0 * Ndim + n) = v;
            }
            if (r1 < M) {
                float2 v = make_float2(acc[mt][j][2] + bx, acc[mt][j][3] + by);
                *reinterpret_cast<float2*>(out + (size_t)r1 * Ndim + n) = v;
            }
        }
    }
}

// ---------------- launch ----------------
extern "C" void kernel_launch(void* const* d_in, const int* in_sizes, int n_in,
                              void* d_out, int out_size) {
    const float* features = (const float*)d_in[0];
    const float* tags     = (const float*)d_in[1];
    const int*   captions = (const int*)d_in[2];
    const int*   lengths  = (const int*)d_in[3];
    const float* W_embed  = (const float*)d_in[4];
    const float* W_ih     = (const float*)d_in[5];
    const float* W_hh     = (const float*)d_in[6];
    const float* b_ih     = (const float*)d_in[7];
    const float* b_hh     = (const float*)d_in[8];
    const float* W_lin    = (const float*)d_in[9];
    const float* b_lin    = (const float*)d_in[10];
    float* out = (float*)d_out;

    int N = out_size / VV;

    const int SMEM = 1024 + 3 * 16384 * 2;   // 99328
    cudaFuncSetAttribute(gemm_f16, cudaFuncAttributeMaxDynamicSharedMemorySize, SMEM);

    h16 *p_hfh, *p_hfl, *p_xh, *p_xl, *p_Wlf, *p_Wih_h, *p_Wih_l, *p_Whh_h, *p_Whh_l, *p_zh;
    float *p_gx, *p_part, *p_bias2;
    int* p_map;
    cudaGetSymbolAddress((void**)&p_hfh, d_hfh);
    cudaGetSymbolAddress((void**)&p_hfl, d_hfl);
    cudaGetSymbolAddress((void**)&p_xh, d_xh);
    cudaGetSymbolAddress((void**)&p_xl, d_xl);
    cudaGetSymbolAddress((void**)&p_Wlf, d_Wlf);
    cudaGetSymbolAddress((void**)&p_Wih_h, d_Wih_h);
    cudaGetSymbolAddress((void**)&p_Wih_l, d_Wih_l);
    cudaGetSymbolAddress((void**)&p_Whh_h, d_Whh_h);
    cudaGetSymbolAddress((void**)&p_Whh_l, d_Whh_l);
    cudaGetSymbolAddress((void**)&p_zh, d_zh);
    cudaGetSymbolAddress((void**)&p_gx, d_gx);
    cudaGetSymbolAddress((void**)&p_part, d_part);
    cudaGetSymbolAddress((void**)&p_bias2, d_bias2);
    cudaGetSymbolAddress((void**)&p_map, d_rowmap);

    meta_kernel<<<1, 128>>>(lengths);
    conv_round<<<(VV * 1024 / 4 + 255) / 256, 256>>>(W_lin, p_Wlf, VV * 1024 / 4);
    conv_split<<<4096, 256>>>(W_ih, p_Wih_h, p_Wih_l, 4096 * 1024 / 4);
    conv_split<<<4096, 256>>>(W_hh, p_Whh_h, p_Whh_l, 4096 * 1024 / 4);
    bias2_k<<<16, 256>>>(b_ih, b_hh);
    conv_xt<<<4096, 256>>>(features, tags, captions, W_embed);

    // gx: 3 segments (xh*Wh + xl*Wh + xh*Wl), M=4096, Ndim=4096
    gemm_f16<<<dim3(32, 32, 1), 256, SMEM>>>(
        p_xh, p_xl, p_xh, p_Wih_h, p_Wih_h, p_Wih_l,
        nullptr, p_bias2, p_gx, 4096, G4, 48, 0);

    // recurrence: per step, 3 segments split 4-way over K -> 128 CTAs
    for (int t = 0; t < TT; t++) {
        const h16* ah = (t == 0) ? p_zh : (p_hfh + (size_t)(t - 1) * BB * 1024);
        const h16* al = (t == 0) ? p_zh : (p_hfl + (size_t)(t - 1) * BB * 1024);
        gemm_f16<<<dim3(32, 1, 4), 256, SMEM>>>(
            ah, al, ah, p_Whh_h, p_Whh_h, p_Whh_l,
            nullptr, nullptr, p_part, BB, G4, 12, (size_t)BB * G4);
        lstm_ew<<<(BB * HH) / 256, 256>>>(t);
    }

    // projection: 2 segments (hh*W + hl*W), rows via rowmap
    gemm_f16<<<dim3((VV + 127) / 128, (N + 127) / 128, 1), 256, SMEM>>>(
        p_hfh, p_hfl, nullptr, p_Wlf, p_Wlf, nullptr,
        p_map, b_lin, out, N, VV, 32, 0);
}

// round 4
// speedup vs baseline: 3.6132x; 1.2214x over previous
#include <cuda_runtime.h>
#include <cuda_fp16.h>
#include <math.h>
#include <stdint.h>

#define BB 128
#define LL 31
#define TT 32
#define EE 512
#define TAGN 512
#define HH 1024
#define G4 4096
#define VV 30000

typedef __half h16;

// ---------------- device scratch ----------------
__device__ __align__(256) float d_gx[(size_t)4096 * 4096];   // [b*32+t][4H]
__device__ __align__(256) float d_part[4][(size_t)BB * G4];  // split-K partials
__device__ __align__(256) float d_c[BB * HH];
__device__ __align__(256) h16 d_hfh[(size_t)4096 * 1024];    // h hi, rows t*128+b
__device__ __align__(256) h16 d_hfl[(size_t)4096 * 1024];    // h lo
__device__ __align__(256) h16 d_xh[(size_t)4096 * 1024];     // xt hi, rows b*32+t
__device__ __align__(256) h16 d_xl[(size_t)4096 * 1024];
__device__ __align__(256) h16 d_Wlf[(size_t)VV * 1024];      // W_lin fp16
__device__ __align__(256) h16 d_Wih_h[(size_t)4096 * 1024];
__device__ __align__(256) h16 d_Wih_l[(size_t)4096 * 1024];
__device__ __align__(256) h16 d_Whh_h[(size_t)4096 * 1024];
__device__ __align__(256) h16 d_Whh_l[(size_t)4096 * 1024];
__device__ __align__(256) float d_bias2[G4];
__device__ int d_rowmap[4096];
__device__ int d_goff[8];            // group row offsets: goff[g] = sum n_t, t < 8g

// ---------------- asm helpers (portable to plain sm_103) ----------------
__device__ __forceinline__ uint32_t smem_u32(const void* p) {
    uint32_t a;
    asm("{ .reg .u64 t; cvta.to.shared.u64 t, %1; cvt.u32.u64 %0, t; }" : "=r"(a) : "l"(p));
    return a;
}
#define CP16(dst, src) asm volatile("cp.async.cg.shared.global [%0], [%1], 16;" :: "r"(dst), "l"(src))
#define CP_COMMIT()    asm volatile("cp.async.commit_group;")
#define CP_WAIT1()     asm volatile("cp.async.wait_group 1;")
#define CP_WAIT0()     asm volatile("cp.async.wait_group 0;")

__device__ __forceinline__ void ldsm4(uint32_t addr, uint32_t* r) {
    asm volatile("ldmatrix.sync.aligned.m8n8.x4.shared.b16 {%0,%1,%2,%3}, [%4];"
                 : "=r"(r[0]), "=r"(r[1]), "=r"(r[2]), "=r"(r[3]) : "r"(addr));
}
__device__ __forceinline__ void mma16816(float* d, const uint32_t* a, uint32_t b0, uint32_t b1) {
    asm volatile(
        "mma.sync.aligned.m16n8k16.row.col.f32.f16.f16.f32 "
        "{%0,%1,%2,%3}, {%4,%5,%6,%7}, {%8,%9}, {%0,%1,%2,%3};"
        : "+f"(d[0]), "+f"(d[1]), "+f"(d[2]), "+f"(d[3])
        : "r"(a[0]), "r"(a[1]), "r"(a[2]), "r"(a[3]), "r"(b0), "r"(b1));
}

// ---------------- small kernels ----------------
__global__ void meta_kernel(const int* __restrict__ lengths) {
    __shared__ int len[BB];
    __shared__ int nt[TT];
    __shared__ int off[TT];
    int tid = threadIdx.x;
    len[tid] = lengths[tid];
    __syncthreads();
    if (tid < TT) {
        int c = 0;
        for (int b = 0; b < BB; b++) c += (len[b] > tid) ? 1 : 0;
        nt[tid] = c;
    }
    __syncthreads();
    if (tid == 0) {
        int s = 0;
        for (int t = 0; t < TT; t++) { off[t] = s; s += nt[t]; }
        for (int g = 0; g <= 4; g++)
            d_goff[g] = (g == 4) ? s : off[g * 8];
    }
    __syncthreads();
    for (int t = 0; t < TT; t++) {
        int n = nt[t], o = off[t];
        for (int b = tid; b < n; b += blockDim.x)
            d_rowmap[o + b] = t * BB + b;
    }
}

__global__ void conv_split(const float* __restrict__ s, h16* __restrict__ hi,
                           h16* __restrict__ lo, int n4) {
    int i = blockIdx.x * blockDim.x + threadIdx.x;
    if (i >= n4) return;
    float4 v = reinterpret_cast<const float4*>(s)[i];
    float vv[4] = {v.x, v.y, v.z, v.w};
    h16 hh[4], ll[4];
#pragma unroll
    for (int j = 0; j < 4; j++) {
        hh[j] = __float2half(vv[j]);
        ll[j] = __float2half(vv[j] - __half2float(hh[j]));
    }
    reinterpret_cast<uint2*>(hi)[i] = *reinterpret_cast<uint2*>(hh);
    reinterpret_cast<uint2*>(lo)[i] = *reinterpret_cast<uint2*>(ll);
}

__global__ void conv_round(const float* __restrict__ s, h16* __restrict__ o, int n4) {
    int i = blockIdx.x * blockDim.x + threadIdx.x;
    if (i >= n4) return;
    float4 v = reinterpret_cast<const float4*>(s)[i];
    h16 hh[4] = {__float2half(v.x), __float2half(v.y), __float2half(v.z), __float2half(v.w)};
    reinterpret_cast<uint2*>(o)[i] = *reinterpret_cast<uint2*>(hh);
}

__global__ void bias2_k(const float* __restrict__ b_ih, const float* __restrict__ b_hh) {
    int i = blockIdx.x * blockDim.x + threadIdx.x;
    if (i < G4) d_bias2[i] = b_ih[i] + b_hh[i];
}

__global__ void conv_xt(const float* __restrict__ features, const float* __restrict__ tags,
                        const int* __restrict__ captions, const float* __restrict__ W_embed) {
    int r = blockIdx.x;            // b*32+t
    int b = r >> 5, t = r & 31;
    int k = threadIdx.x * 4;
    const float* src;
    int kk = k;
    if (k < EE) {
        src = (t == 0) ? (features + (size_t)b * EE)
                       : (W_embed + (size_t)captions[b * LL + (t - 1)] * EE);
    } else {
        src = tags + (size_t)b * TAGN;
        kk = k - EE;
    }
    float4 v = *reinterpret_cast<const float4*>(src + kk);
    float vv[4] = {v.x, v.y, v.z, v.w};
    h16 hh[4], ll[4];
#pragma unroll
    for (int j = 0; j < 4; j++) {
        hh[j] = __float2half(vv[j]);
        ll[j] = __float2half(vv[j] - __half2float(hh[j]));
    }
    size_t o = ((size_t)r * 1024 + k) >> 2;
    reinterpret_cast<uint2*>(d_xh)[o] = *reinterpret_cast<uint2*>(hh);
    reinterpret_cast<uint2*>(d_xl)[o] = *reinterpret_cast<uint2*>(ll);
}

// LSTM elementwise; has_part=0 at t=0 (no recurrent contribution)
__global__ void lstm_ew(int t, int has_part) {
    int idx = blockIdx.x * blockDim.x + threadIdx.x;
    int b = idx >> 10, j = idx & 1023;
    size_t gxr = (size_t)(b * TT + t) * G4 + j;
    size_t gr = (size_t)b * G4 + j;
    float gi = d_gx[gxr], gf = d_gx[gxr + 1024], gg = d_gx[gxr + 2048], go = d_gx[gxr + 3072];
    if (has_part) {
#pragma unroll
        for (int s = 0; s < 4; s++) {
            gi += d_part[s][gr];
            gf += d_part[s][gr + 1024];
            gg += d_part[s][gr + 2048];
            go += d_part[s][gr + 3072];
        }
    }
    float i_ = 1.f / (1.f + expf(-gi));
    float f_ = 1.f / (1.f + expf(-gf));
    float g_ = tanhf(gg);
    float o_ = 1.f / (1.f + expf(-go));
    float c = i_ * g_ + (t ? f_ * d_c[idx] : 0.f);
    d_c[idx] = c;
    float h = o_ * tanhf(c);
    size_t hr = (size_t)(t * BB + b) * 1024 + j;
    h16 hh = __float2half(h);
    d_hfh[hr] = hh;
    d_hfl[hr] = __float2half(h - __half2float(hh));
}

// ---------------- HMMA GEMM ----------------
// out[m][n] (+bias[n]) = sum_seg sum_k Aseg[arow[m]][k] * Bseg[n][k]
// chunk c: seg = c>>4 selects (A0,B0)/(A1,B1)/(A2,B2); kc = (c&15)*64.
// BM=BN=128, 8 warps 2x4, warp tile 64x32, 3-stage cp.async pipeline.
// blockIdx.z: split-K over chunk list, writes out + z*zstride.
// grange (optional): device {start,end} row window (timestep-group slicing).
__global__ __launch_bounds__(256) void gemm_f16(
    const h16* __restrict__ A0, const h16* __restrict__ A1, const h16* __restrict__ A2,
    const h16* __restrict__ B0, const h16* __restrict__ B1, const h16* __restrict__ B2,
    const int* __restrict__ map, const float* __restrict__ bias,
    float* __restrict__ out, int M, int Ndim, int cpz, size_t zstride,
    const int* __restrict__ grange)
{
    extern __shared__ char sm[];
    int* arow = reinterpret_cast<int*>(sm);
    uint32_t smu = smem_u32(sm);
    const uint32_t aA = smu + 1024;
    const uint32_t aB = aA + 3 * 16384;

    int tid = threadIdx.x;
    int lane = tid & 31;
    int w = tid >> 5;
    int wm = w >> 2, wn = w & 3;      // 2 x 4 warp grid
    int n0 = blockIdx.x * 128;
    int m0 = blockIdx.y * 128;
    int Mlim = M;
    if (grange) {
        int gs = grange[0], ge = grange[1];
        m0 = gs + blockIdx.y * 128;
        Mlim = ge;
        if (m0 >= ge) return;
    }
    int c0 = blockIdx.z * cpz;
    int c1 = c0 + cpz;
    out += (size_t)blockIdx.z * zstride;

    if (tid < 128) {
        int mm = m0 + tid;
        if (mm >= Mlim) mm = Mlim - 1;
        arow[tid] = map ? map[mm] : mm;
    }
    __syncthreads();

    auto load_chunk = [&](int chunk, int stage) {
        int seg = chunk >> 4;
        int kc = (chunk & 15) * 64;
        const h16* Ap = (seg == 0) ? A0 : (seg == 1) ? A1 : A2;
        const h16* Bp = (seg == 0) ? B0 : (seg == 1) ? B1 : B2;
        uint32_t da = aA + stage * 16384;
        uint32_t db = aB + stage * 16384;
#pragma unroll
        for (int q = 0; q < 4; q++) {
            int idx = q * 256 + tid;
            int row = idx >> 3, c = idx & 7;
            const h16* src = Ap + (size_t)arow[row] * 1024 + kc + c * 8;
            CP16(da + row * 128 + ((c ^ (row & 7)) * 16), src);
        }
#pragma unroll
        for (int q = 0; q < 4; q++) {
            int idx = q * 256 + tid;
            int row = idx >> 3, c = idx & 7;
            int vr = n0 + row;
            if (vr >= Ndim) vr = Ndim - 1;
            const h16* src = Bp + (size_t)vr * 1024 + kc + c * 8;
            CP16(db + row * 128 + ((c ^ (row & 7)) * 16), src);
        }
        CP_COMMIT();
    };

    float acc[4][4][4];
#pragma unroll
    for (int i = 0; i < 4; i++)
#pragma unroll
        for (int j = 0; j < 4; j++)
#pragma unroll
            for (int k = 0; k < 4; k++) acc[i][j][k] = 0.f;

    load_chunk(c0, 0);
    if (c0 + 1 < c1) load_chunk(c0 + 1, 1);

    int lrow = lane & 15;
    int lcol = lane >> 4;

    for (int i = c0; i < c1; i++) {
        if (i + 1 < c1) { CP_WAIT1(); } else { CP_WAIT0(); }
        __syncthreads();
        if (i + 2 < c1) load_chunk(i + 2, (i + 2 - c0) % 3);

        int stage = (i - c0) % 3;
        uint32_t ab = aA + stage * 16384;
        uint32_t bb = aB + stage * 16384;
#pragma unroll
        for (int k16 = 0; k16 < 4; k16++) {
            uint32_t af[4][4];
#pragma unroll
            for (int mt = 0; mt < 4; mt++) {
                int r = wm * 64 + mt * 16 + lrow;
                int c = (k16 * 2 + lcol) ^ (r & 7);
                ldsm4(ab + r * 128 + c * 16, af[mt]);
            }
            uint32_t bf[2][4];
#pragma unroll
            for (int bt = 0; bt < 2; bt++) {
                int r = wn * 32 + bt * 16 + lrow;
                int c = (k16 * 2 + lcol) ^ (r & 7);
                ldsm4(bb + r * 128 + c * 16, bf[bt]);
            }
#pragma unroll
            for (int mt = 0; mt < 4; mt++)
#pragma unroll
                for (int bt = 0; bt < 2; bt++) {
                    mma16816(acc[mt][bt * 2],     af[mt], bf[bt][0], bf[bt][2]);
                    mma16816(acc[mt][bt * 2 + 1], af[mt], bf[bt][1], bf[bt][3]);
                }
        }
        __syncthreads();
    }

    int gr = lane >> 2;
    int gc = (lane & 3) * 2;
#pragma unroll
    for (int mt = 0; mt < 4; mt++) {
        int r0 = m0 + wm * 64 + mt * 16 + gr;
        int r1 = r0 + 8;
#pragma unroll
        for (int j = 0; j < 4; j++) {
            int n = n0 + wn * 32 + j * 8 + gc;
            if (n >= Ndim) continue;
            float bx = 0.f, by = 0.f;
            if (bias) { float2 bv = *reinterpret_cast<const float2*>(bias + n); bx = bv.x; by = bv.y; }
            if (r0 < Mlim) {
                float2 v = make_float2(acc[mt][j][0] + bx, acc[mt][j][1] + by);
                *reinterpret_cast<float2*>(out + (size_t)r0 * Ndim + n) = v;
            }
            if (r1 < Mlim) {
                float2 v = make_float2(acc[mt][j][2] + bx, acc[mt][j][3] + by);
                *reinterpret_cast<float2*>(out + (size_t)r1 * Ndim + n) = v;
            }
        }
    }
}

// ---------------- launch ----------------
extern "C" void kernel_launch(void* const* d_in, const int* in_sizes, int n_in,
                              void* d_out, int out_size) {
    const float* features = (const float*)d_in[0];
    const float* tags     = (const float*)d_in[1];
    const int*   captions = (const int*)d_in[2];
    const int*   lengths  = (const int*)d_in[3];
    const float* W_embed  = (const float*)d_in[4];
    const float* W_ih     = (const float*)d_in[5];
    const float* W_hh     = (const float*)d_in[6];
    const float* b_ih     = (const float*)d_in[7];
    const float* b_hh     = (const float*)d_in[8];
    const float* W_lin    = (const float*)d_in[9];
    const float* b_lin    = (const float*)d_in[10];
    float* out = (float*)d_out;

    int N = out_size / VV;

    const int SMEM = 1024 + 3 * 16384 * 2;   // 99328
    static bool once = false;
    static cudaStream_t sA = 0, sB = 0;      // sA: high-prio rec chain; sB: low-prio proj
    static cudaEvent_t evF, evM, evG[4], evJA, evJB;
    if (!once) {
        cudaFuncSetAttribute(gemm_f16, cudaFuncAttributeMaxDynamicSharedMemorySize, SMEM);
        int lo, hi;
        cudaDeviceGetStreamPriorityRange(&lo, &hi);
        cudaStreamCreateWithPriority(&sA, cudaStreamNonBlocking, hi);
        cudaStreamCreateWithPriority(&sB, cudaStreamNonBlocking, lo);
        cudaEventCreateWithFlags(&evF, cudaEventDisableTiming);
        cudaEventCreateWithFlags(&evM, cudaEventDisableTiming);
        for (int g = 0; g < 4; g++) cudaEventCreateWithFlags(&evG[g], cudaEventDisableTiming);
        cudaEventCreateWithFlags(&evJA, cudaEventDisableTiming);
        cudaEventCreateWithFlags(&evJB, cudaEventDisableTiming);
        once = true;
    }

    h16 *p_hfh, *p_hfl, *p_xh, *p_xl, *p_Wlf, *p_Wih_h, *p_Wih_l, *p_Whh_h, *p_Whh_l;
    float *p_gx, *p_part, *p_bias2;
    int *p_map, *p_goff;
    cudaGetSymbolAddress((void**)&p_hfh, d_hfh);
    cudaGetSymbolAddress((void**)&p_hfl, d_hfl);
    cudaGetSymbolAddress((void**)&p_xh, d_xh);
    cudaGetSymbolAddress((void**)&p_xl, d_xl);
    cudaGetSymbolAddress((void**)&p_Wlf, d_Wlf);
    cudaGetSymbolAddress((void**)&p_Wih_h, d_Wih_h);
    cudaGetSymbolAddress((void**)&p_Wih_l, d_Wih_l);
    cudaGetSymbolAddress((void**)&p_Whh_h, d_Whh_h);
    cudaGetSymbolAddress((void**)&p_Whh_l, d_Whh_l);
    cudaGetSymbolAddress((void**)&p_gx, d_gx);
    cudaGetSymbolAddress((void**)&p_part, d_part);
    cudaGetSymbolAddress((void**)&p_bias2, d_bias2);
    cudaGetSymbolAddress((void**)&p_map, d_rowmap);
    cudaGetSymbolAddress((void**)&p_goff, d_goff);

    // fork both worker streams off the capture stream
    cudaEventRecord(evF, 0);
    cudaStreamWaitEvent(sA, evF, 0);
    cudaStreamWaitEvent(sB, evF, 0);

    // ---- sA: meta + conversions + gx + recurrence ----
    meta_kernel<<<1, 128, 0, sA>>>(lengths);
    cudaEventRecord(evM, sA);
    conv_split<<<4096, 256, 0, sA>>>(W_ih, p_Wih_h, p_Wih_l, 4096 * 1024 / 4);
    conv_split<<<4096, 256, 0, sA>>>(W_hh, p_Whh_h, p_Whh_l, 4096 * 1024 / 4);
    bias2_k<<<16, 256, 0, sA>>>(b_ih, b_hh);
    conv_xt<<<4096, 256, 0, sA>>>(features, tags, captions, W_embed);

    // gx: 3 segments (xh*Wh + xl*Wh + xh*Wl), M=4096, Ndim=4096
    gemm_f16<<<dim3(32, 32, 1), 256, SMEM, sA>>>(
        p_xh, p_xl, p_xh, p_Wih_h, p_Wih_h, p_Wih_l,
        nullptr, p_bias2, p_gx, 4096, G4, 48, 0, nullptr);

    for (int t = 0; t < TT; t++) {
        if (t > 0) {
            const h16* ah = p_hfh + (size_t)(t - 1) * BB * 1024;
            const h16* al = p_hfl + (size_t)(t - 1) * BB * 1024;
            gemm_f16<<<dim3(32, 1, 4), 256, SMEM, sA>>>(
                ah, al, ah, p_Whh_h, p_Whh_h, p_Whh_l,
                nullptr, nullptr, p_part, BB, G4, 12, (size_t)BB * G4, nullptr);
        }
        lstm_ew<<<(BB * HH) / 256, 256, 0, sA>>>(t, t > 0 ? 1 : 0);
        if ((t & 7) == 7) cudaEventRecord(evG[t >> 3], sA);
    }

    // ---- sB: W_lin conversion + projection groups (single fp16 pass) ----
    conv_round<<<(VV * 1024 / 4 + 255) / 256, 256, 0, sB>>>(W_lin, p_Wlf, VV * 1024 / 4);
    cudaStreamWaitEvent(sB, evM, 0);
    for (int g = 0; g < 4; g++) {
        cudaStreamWaitEvent(sB, evG[g], 0);
        gemm_f16<<<dim3((VV + 127) / 128, 8, 1), 256, SMEM, sB>>>(
            p_hfh, p_hfh, p_hfh, p_Wlf, p_Wlf, p_Wlf,
            p_map, b_lin, out, N, VV, 16, 0, p_goff + g);
    }

    // join back to the capture stream
    cudaEventRecord(evJA, sA);
    cudaEventRecord(evJB, sB);
    cudaStreamWaitEvent(0, evJA, 0);
    cudaStreamWaitEvent(0, evJB, 0);
}

// round 6
// speedup vs baseline: 3.8625x; 1.0690x over previous
#include <cuda_runtime.h>
#include <cuda_fp16.h>
#include <math.h>
#include <stdint.h>

#define BB 128
#define LL 31
#define TT 32
#define EE 512
#define TAGN 512
#define HH 1024
#define G4 4096
#define VV 30000

typedef __half h16;

// ---------------- device scratch ----------------
__device__ __align__(256) float d_gx[3][(size_t)4096 * 4096];   // embed-gx, 3 segments, rows t*128+b
__device__ __align__(256) float d_gxt[3][(size_t)BB * G4];      // tag-gx, 3 segments, rows b
__device__ __align__(256) float d_part[4][(size_t)BB * G4];     // rec split-K partials
__device__ __align__(256) float d_c[BB * HH];
__device__ __align__(256) h16 d_hfh[(size_t)4096 * 1024];       // h hi, rows t*128+b
__device__ __align__(256) h16 d_hfl[(size_t)4096 * 1024];       // h lo
__device__ __align__(256) h16 d_xeh[(size_t)4096 * 512];        // x embed-part hi, rows t*128+b
__device__ __align__(256) h16 d_xel[(size_t)4096 * 512];
__device__ __align__(256) h16 d_tgh[(size_t)BB * 512];          // tags hi/lo
__device__ __align__(256) h16 d_tgl[(size_t)BB * 512];
__device__ __align__(256) h16 d_Wlf[(size_t)VV * 1024];         // W_lin fp16
__device__ __align__(256) h16 d_Wieh[(size_t)4096 * 512];       // W_ih embed cols hi/lo
__device__ __align__(256) h16 d_Wiel[(size_t)4096 * 512];
__device__ __align__(256) h16 d_With[(size_t)4096 * 512];       // W_ih tag cols hi/lo
__device__ __align__(256) h16 d_Witl[(size_t)4096 * 512];
__device__ __align__(256) h16 d_Whhh[(size_t)4096 * 1024];      // W_hh hi/lo
__device__ __align__(256) h16 d_Whhl[(size_t)4096 * 1024];
__device__ __align__(256) float d_bias2[G4];
__device__ int d_rowmap[4096];

// ---------------- asm helpers (portable to plain sm_103) ----------------
__device__ __forceinline__ uint32_t smem_u32(const void* p) {
    uint32_t a;
    asm("{ .reg .u64 t; cvta.to.shared.u64 t, %1; cvt.u32.u64 %0, t; }" : "=r"(a) : "l"(p));
    return a;
}
#define CP16(dst, src) asm volatile("cp.async.cg.shared.global [%0], [%1], 16;" :: "r"(dst), "l"(src))
#define CP_COMMIT()    asm volatile("cp.async.commit_group;")
#define CP_WAIT1()     asm volatile("cp.async.wait_group 1;")
#define CP_WAIT0()     asm volatile("cp.async.wait_group 0;")

__device__ __forceinline__ void ldsm4(uint32_t addr, uint32_t* r) {
    asm volatile("ldmatrix.sync.aligned.m8n8.x4.shared.b16 {%0,%1,%2,%3}, [%4];"
                 : "=r"(r[0]), "=r"(r[1]), "=r"(r[2]), "=r"(r[3]) : "r"(addr));
}
__device__ __forceinline__ void mma16816(float* d, const uint32_t* a, uint32_t b0, uint32_t b1) {
    asm volatile(
        "mma.sync.aligned.m16n8k16.row.col.f32.f16.f16.f32 "
        "{%0,%1,%2,%3}, {%4,%5,%6,%7}, {%8,%9}, {%0,%1,%2,%3};"
        : "+f"(d[0]), "+f"(d[1]), "+f"(d[2]), "+f"(d[3])
        : "r"(a[0]), "r"(a[1]), "r"(a[2]), "r"(a[3]), "r"(b0), "r"(b1));
}

// ---------------- small kernels ----------------
__global__ void meta_kernel(const int* __restrict__ lengths) {
    __shared__ int len[BB];
    __shared__ int nt[TT];
    __shared__ int off[TT];
    int tid = threadIdx.x;
    len[tid] = lengths[tid];
    __syncthreads();
    if (tid < TT) {
        int c = 0;
        for (int b = 0; b < BB; b++) c += (len[b] > tid) ? 1 : 0;
        nt[tid] = c;
    }
    __syncthreads();
    if (tid == 0) {
        int s = 0;
        for (int t = 0; t < TT; t++) { off[t] = s; s += nt[t]; }
    }
    __syncthreads();
    for (int t = 0; t < TT; t++) {
        int n = nt[t], o = off[t];
        for (int b = tid; b < n; b += blockDim.x)
            d_rowmap[o + b] = t * BB + b;
    }
}

// generic fp32 -> fp16 hi/lo split
__global__ void conv_split(const float* __restrict__ s, h16* __restrict__ hi,
                           h16* __restrict__ lo, int n4) {
    int i = blockIdx.x * blockDim.x + threadIdx.x;
    if (i >= n4) return;
    float4 v = reinterpret_cast<const float4*>(s)[i];
    float vv[4] = {v.x, v.y, v.z, v.w};
    h16 hh[4], ll[4];
#pragma unroll
    for (int j = 0; j < 4; j++) {
        hh[j] = __float2half(vv[j]);
        ll[j] = __float2half(vv[j] - __half2float(hh[j]));
    }
    reinterpret_cast<uint2*>(hi)[i] = *reinterpret_cast<uint2*>(hh);
    reinterpret_cast<uint2*>(lo)[i] = *reinterpret_cast<uint2*>(ll);
}

// fp32 -> fp16 round (single)
__global__ void conv_round(const float* __restrict__ s, h16* __restrict__ o, int n4) {
    int i = blockIdx.x * blockDim.x + threadIdx.x;
    if (i >= n4) return;
    float4 v = reinterpret_cast<const float4*>(s)[i];
    h16 hh[4] = {__float2half(v.x), __float2half(v.y), __float2half(v.z), __float2half(v.w)};
    reinterpret_cast<uint2*>(o)[i] = *reinterpret_cast<uint2*>(hh);
}

// split W_ih [4096][1024] column-wise into embed (k<512) and tag (k>=512) hi/lo
__global__ void conv_wih(const float* __restrict__ W_ih) {
    int row = blockIdx.x;
    int k = threadIdx.x * 4;
    float4 v = *reinterpret_cast<const float4*>(W_ih + (size_t)row * 1024 + k);
    float vv[4] = {v.x, v.y, v.z, v.w};
    h16 hh[4], ll[4];
#pragma unroll
    for (int j = 0; j < 4; j++) {
        hh[j] = __float2half(vv[j]);
        ll[j] = __float2half(vv[j] - __half2float(hh[j]));
    }
    if (k < EE) {
        size_t o = ((size_t)row * 512 + k) >> 2;
        reinterpret_cast<uint2*>(d_Wieh)[o] = *reinterpret_cast<uint2*>(hh);
        reinterpret_cast<uint2*>(d_Wiel)[o] = *reinterpret_cast<uint2*>(ll);
    } else {
        size_t o = ((size_t)row * 512 + (k - EE)) >> 2;
        reinterpret_cast<uint2*>(d_With)[o] = *reinterpret_cast<uint2*>(hh);
        reinterpret_cast<uint2*>(d_Witl)[o] = *reinterpret_cast<uint2*>(ll);
    }
}

__global__ void bias2_k(const float* __restrict__ b_ih, const float* __restrict__ b_hh) {
    int i = blockIdx.x * blockDim.x + threadIdx.x;
    if (i < G4) d_bias2[i] = b_ih[i] + b_hh[i];
}

// gather embed-part x rows (features for t=0, embeddings else), rows t*128+b
__global__ void conv_xt(const float* __restrict__ features,
                        const int* __restrict__ captions, const float* __restrict__ W_embed) {
    int r = blockIdx.x;
    int t = r >> 7, b = r & 127;
    int k = threadIdx.x * 4;
    const float* src = (t == 0) ? (features + (size_t)b * EE)
                                : (W_embed + (size_t)captions[b * LL + (t - 1)] * EE);
    float4 v = *reinterpret_cast<const float4*>(src + k);
    float vv[4] = {v.x, v.y, v.z, v.w};
    h16 hh[4], ll[4];
#pragma unroll
    for (int j = 0; j < 4; j++) {
        hh[j] = __float2half(vv[j]);
        ll[j] = __float2half(vv[j] - __half2float(hh[j]));
    }
    size_t o = ((size_t)r * 512 + k) >> 2;
    reinterpret_cast<uint2*>(d_xeh)[o] = *reinterpret_cast<uint2*>(hh);
    reinterpret_cast<uint2*>(d_xel)[o] = *reinterpret_cast<uint2*>(ll);
}

// split tags [128][512] hi/lo
__global__ void conv_tags(const float* __restrict__ tags) {
    int b = blockIdx.x;
    int k = threadIdx.x * 4;
    float4 v = *reinterpret_cast<const float4*>(tags + (size_t)b * TAGN + k);
    float vv[4] = {v.x, v.y, v.z, v.w};
    h16 hh[4], ll[4];
#pragma unroll
    for (int j = 0; j < 4; j++) {
        hh[j] = __float2half(vv[j]);
        ll[j] = __float2half(vv[j] - __half2float(hh[j]));
    }
    size_t o = ((size_t)b * 512 + k) >> 2;
    reinterpret_cast<uint2*>(d_tgh)[o] = *reinterpret_cast<uint2*>(hh);
    reinterpret_cast<uint2*>(d_tgl)[o] = *reinterpret_cast<uint2*>(ll);
}

// LSTM elementwise: gates = sum3 gx(embed,row t*128+b) + sum3 gxt(row b, incl bias)
//                         + sum_{s<np} part[s]; h -> fp16 hi/lo
__global__ void lstm_ew(int t, int np) {
    int idx = blockIdx.x * blockDim.x + threadIdx.x;
    int b = idx >> 10, j = idx & 1023;
    size_t gxr = (size_t)(t * BB + b) * G4 + j;
    size_t gr = (size_t)b * G4 + j;
    float gi = 0.f, gf = 0.f, gg = 0.f, go = 0.f;
#pragma unroll
    for (int s = 0; s < 3; s++) {
        gi += d_gx[s][gxr]        + d_gxt[s][gr];
        gf += d_gx[s][gxr + 1024] + d_gxt[s][gr + 1024];
        gg += d_gx[s][gxr + 2048] + d_gxt[s][gr + 2048];
        go += d_gx[s][gxr + 3072] + d_gxt[s][gr + 3072];
    }
    for (int s = 0; s < np; s++) {
        gi += d_part[s][gr];
        gf += d_part[s][gr + 1024];
        gg += d_part[s][gr + 2048];
        go += d_part[s][gr + 3072];
    }
    float i_ = 1.f / (1.f + expf(-gi));
    float f_ = 1.f / (1.f + expf(-gf));
    float g_ = tanhf(gg);
    float o_ = 1.f / (1.f + expf(-go));
    float c = i_ * g_ + (t ? f_ * d_c[idx] : 0.f);
    d_c[idx] = c;
    float h = o_ * tanhf(c);
    size_t hr = (size_t)(t * BB + b) * 1024 + j;
    h16 hh = __float2half(h);
    d_hfh[hr] = hh;
    d_hfl[hr] = __float2half(h - __half2float(hh));
}

// ---------------- HMMA GEMM ----------------
// out[m][n] (+bias[n], z==0 only) = sum_c Aseg[arow[m]]*Bseg[n] over chunk list.
// chunk c: seg = c / kps, kc = (c % kps) * 64. Aseg/Bseg row strides Astr/Bstr.
// BM=BN=128, 8 warps 2x4, 3-stage cp.async pipeline.
// blockIdx.z handles chunks [z*cpz,(z+1)*cpz), writes out + z*zstride.
__global__ __launch_bounds__(256) void gemm_f16(
    const h16* __restrict__ A0, const h16* __restrict__ A1, const h16* __restrict__ A2,
    const h16* __restrict__ B0, const h16* __restrict__ B1, const h16* __restrict__ B2,
    const int* __restrict__ map, const float* __restrict__ bias,
    float* __restrict__ out, int M, int Ndim, int cpz, size_t zstride,
    int m_base, int kps, int Astr, int Bstr)
{
    extern __shared__ char sm[];
    int* arow = reinterpret_cast<int*>(sm);
    uint32_t smu = smem_u32(sm);
    const uint32_t aA = smu + 1024;
    const uint32_t aB = aA + 3 * 16384;

    int tid = threadIdx.x;
    int lane = tid & 31;
    int w = tid >> 5;
    int wm = w >> 2, wn = w & 3;
    int n0 = blockIdx.x * 128;
    int m0 = m_base + blockIdx.y * 128;
    int c0 = blockIdx.z * cpz;
    int c1 = c0 + cpz;
    out += (size_t)blockIdx.z * zstride;
    const float* bias_eff = (blockIdx.z == 0) ? bias : nullptr;

    if (tid < 128) {
        int mm = m0 + tid;
        if (mm >= M) mm = M - 1;
        arow[tid] = map ? map[mm] : mm;
    }
    __syncthreads();

    auto load_chunk = [&](int chunk, int stage) {
        int seg = chunk / kps;
        int kc = (chunk - seg * kps) * 64;
        const h16* Ap = (seg == 0) ? A0 : (seg == 1) ? A1 : A2;
        const h16* Bp = (seg == 0) ? B0 : (seg == 1) ? B1 : B2;
        uint32_t da = aA + stage * 16384;
        uint32_t db = aB + stage * 16384;
#pragma unroll
        for (int q = 0; q < 4; q++) {
            int idx = q * 256 + tid;
            int row = idx >> 3, c = idx & 7;
            const h16* src = Ap + (size_t)arow[row] * Astr + kc + c * 8;
            CP16(da + row * 128 + ((c ^ (row & 7)) * 16), src);
        }
#pragma unroll
        for (int q = 0; q < 4; q++) {
            int idx = q * 256 + tid;
            int row = idx >> 3, c = idx & 7;
            int vr = n0 + row;
            if (vr >= Ndim) vr = Ndim - 1;
            const h16* src = Bp + (size_t)vr * Bstr + kc + c * 8;
            CP16(db + row * 128 + ((c ^ (row & 7)) * 16), src);
        }
        CP_COMMIT();
    };

    float acc[4][4][4];
#pragma unroll
    for (int i = 0; i < 4; i++)
#pragma unroll
        for (int j = 0; j < 4; j++)
#pragma unroll
            for (int k = 0; k < 4; k++) acc[i][j][k] = 0.f;

    load_chunk(c0, 0);
    if (c0 + 1 < c1) load_chunk(c0 + 1, 1);

    int lrow = lane & 15;
    int lcol = lane >> 4;

    for (int i = c0; i < c1; i++) {
        if (i + 1 < c1) { CP_WAIT1(); } else { CP_WAIT0(); }
        __syncthreads();
        if (i + 2 < c1) load_chunk(i + 2, (i + 2 - c0) % 3);

        int stage = (i - c0) % 3;
        uint32_t ab = aA + stage * 16384;
        uint32_t bb = aB + stage * 16384;
#pragma unroll
        for (int k16 = 0; k16 < 4; k16++) {
            uint32_t af[4][4];
#pragma unroll
            for (int mt = 0; mt < 4; mt++) {
                int r = wm * 64 + mt * 16 + lrow;
                int c = (k16 * 2 + lcol) ^ (r & 7);
                ldsm4(ab + r * 128 + c * 16, af[mt]);
            }
            uint32_t bf[2][4];
#pragma unroll
            for (int bt = 0; bt < 2; bt++) {
                int r = wn * 32 + bt * 16 + lrow;
                int c = (k16 * 2 + lcol) ^ (r & 7);
                ldsm4(bb + r * 128 + c * 16, bf[bt]);
            }
#pragma unroll
            for (int mt = 0; mt < 4; mt++)
#pragma unroll
                for (int bt = 0; bt < 2; bt++) {
                    mma16816(acc[mt][bt * 2],     af[mt], bf[bt][0], bf[bt][2]);
                    mma16816(acc[mt][bt * 2 + 1], af[mt], bf[bt][1], bf[bt][3]);
                }
        }
        __syncthreads();
    }

    int gr = lane >> 2;
    int gc = (lane & 3) * 2;
#pragma unroll
    for (int mt = 0; mt < 4; mt++) {
        int r0 = m0 + wm * 64 + mt * 16 + gr;
        int r1 = r0 + 8;
#pragma unroll
        for (int j = 0; j < 4; j++) {
            int n = n0 + wn * 32 + j * 8 + gc;
            if (n >= Ndim) continue;
            float bx = 0.f, by = 0.f;
            if (bias_eff) { float2 bv = *reinterpret_cast<const float2*>(bias_eff + n); bx = bv.x; by = bv.y; }
            if (r0 < M) {
                float2 v = make_float2(acc[mt][j][0] + bx, acc[mt][j][1] + by);
                *reinterpret_cast<float2*>(out + (size_t)r0 * Ndim + n) = v;
            }
            if (r1 < M) {
                float2 v = make_float2(acc[mt][j][2] + bx, acc[mt][j][3] + by);
                *reinterpret_cast<float2*>(out + (size_t)r1 * Ndim + n) = v;
            }
        }
    }
}

// ---------------- launch ----------------
extern "C" void kernel_launch(void* const* d_in, const int* in_sizes, int n_in,
                              void* d_out, int out_size) {
    const float* features = (const float*)d_in[0];
    const float* tags     = (const float*)d_in[1];
    const int*   captions = (const int*)d_in[2];
    const int*   lengths  = (const int*)d_in[3];
    const float* W_embed  = (const float*)d_in[4];
    const float* W_ih     = (const float*)d_in[5];
    const float* W_hh     = (const float*)d_in[6];
    const float* b_ih     = (const float*)d_in[7];
    const float* b_hh     = (const float*)d_in[8];
    const float* W_lin    = (const float*)d_in[9];
    const float* b_lin    = (const float*)d_in[10];
    float* out = (float*)d_out;

    int N = out_size / VV;

    const int SMEM = 1024 + 3 * 16384 * 2;   // 99328
    static bool once = false;
    static cudaStream_t sA = 0, sB = 0;      // sA: hi-prio chain; sB: lo-prio gx
    static cudaEvent_t evF, evW, evX0, evX1, evJA, evJB;
    if (!once) {
        cudaFuncSetAttribute(gemm_f16, cudaFuncAttributeMaxDynamicSharedMemorySize, SMEM);
        int lo, hi;
        cudaDeviceGetStreamPriorityRange(&lo, &hi);
        cudaStreamCreateWithPriority(&sA, cudaStreamNonBlocking, hi);
        cudaStreamCreateWithPriority(&sB, cudaStreamNonBlocking, lo);
        cudaEventCreateWithFlags(&evF, cudaEventDisableTiming);
        cudaEventCreateWithFlags(&evW, cudaEventDisableTiming);
        cudaEventCreateWithFlags(&evX0, cudaEventDisableTiming);
        cudaEventCreateWithFlags(&evX1, cudaEventDisableTiming);
        cudaEventCreateWithFlags(&evJA, cudaEventDisableTiming);
        cudaEventCreateWithFlags(&evJB, cudaEventDisableTiming);
        once = true;
    }

    h16 *p_hfh, *p_hfl, *p_xeh, *p_xel, *p_tgh, *p_tgl, *p_Wlf;
    h16 *p_Wieh, *p_Wiel, *p_With, *p_Witl, *p_Whhh, *p_Whhl;
    float *p_gx, *p_gxt, *p_part, *p_bias2;
    int* p_map;
    cudaGetSymbolAddress((void**)&p_hfh, d_hfh);
    cudaGetSymbolAddress((void**)&p_hfl, d_hfl);
    cudaGetSymbolAddress((void**)&p_xeh, d_xeh);
    cudaGetSymbolAddress((void**)&p_xel, d_xel);
    cudaGetSymbolAddress((void**)&p_tgh, d_tgh);
    cudaGetSymbolAddress((void**)&p_tgl, d_tgl);
    cudaGetSymbolAddress((void**)&p_Wlf, d_Wlf);
    cudaGetSymbolAddress((void**)&p_Wieh, d_Wieh);
    cudaGetSymbolAddress((void**)&p_Wiel, d_Wiel);
    cudaGetSymbolAddress((void**)&p_With, d_With);
    cudaGetSymbolAddress((void**)&p_Witl, d_Witl);
    cudaGetSymbolAddress((void**)&p_Whhh, d_Whhh);
    cudaGetSymbolAddress((void**)&p_Whhl, d_Whhl);
    cudaGetSymbolAddress((void**)&p_gx, d_gx);
    cudaGetSymbolAddress((void**)&p_gxt, d_gxt);
    cudaGetSymbolAddress((void**)&p_part, d_part);
    cudaGetSymbolAddress((void**)&p_bias2, d_bias2);
    cudaGetSymbolAddress((void**)&p_map, d_rowmap);

    const size_t GXZ = (size_t)4096 * 4096;     // gx segment stride
    const size_t GTZ = (size_t)BB * G4;         // gxt / part segment stride

    // fork worker streams
    cudaEventRecord(evF, 0);
    cudaStreamWaitEvent(sA, evF, 0);
    cudaStreamWaitEvent(sB, evF, 0);

    // ---- sB (lo-prio): W_ih split, x gather, gx-embed in 2 row-halves ----
    conv_wih<<<4096, 256, 0, sB>>>(W_ih);
    cudaEventRecord(evW, sB);
    conv_xt<<<4096, 128, 0, sB>>>(features, captions, W_embed);
    // gx-embed half 0: rows t<16 (m 0..2047). 3 segs x 8 chunks (K=512), z=3.
    gemm_f16<<<dim3(32, 16, 3), 256, SMEM, sB>>>(
        p_xeh, p_xel, p_xeh, p_Wieh, p_Wieh, p_Wiel,
        nullptr, nullptr, p_gx, 4096, G4, 8, GXZ, 0, 8, 512, 512);
    cudaEventRecord(evX0, sB);
    gemm_f16<<<dim3(32, 16, 3), 256, SMEM, sB>>>(
        p_xeh, p_xel, p_xeh, p_Wieh, p_Wieh, p_Wiel,
        nullptr, nullptr, p_gx, 4096, G4, 8, GXZ, 2048, 8, 512, 512);
    cudaEventRecord(evX1, sB);

    // ---- sA (hi-prio): meta, conversions, tag-gx, recurrence, projection ----
    meta_kernel<<<1, 128, 0, sA>>>(lengths);
    conv_split<<<4096, 256, 0, sA>>>(W_hh, p_Whhh, p_Whhl, 4096 * 1024 / 4);
    conv_round<<<(VV * 1024 / 4 + 255) / 256, 256, 0, sA>>>(W_lin, p_Wlf, VV * 1024 / 4);
    conv_tags<<<128, 128, 0, sA>>>(tags);
    bias2_k<<<16, 256, 0, sA>>>(b_ih, b_hh);
    cudaStreamWaitEvent(sA, evW, 0);
    // tag-gx: M=128 rows, includes bias2 (seg 0)
    gemm_f16<<<dim3(32, 1, 3), 256, SMEM, sA>>>(
        p_tgh, p_tgl, p_tgh, p_With, p_With, p_Witl,
        nullptr, p_bias2, p_gxt, BB, G4, 8, GTZ, 0, 8, 512, 512);

    cudaStreamWaitEvent(sA, evX0, 0);
    for (int t = 0; t < TT; t++) {
        if (t == 16) cudaStreamWaitEvent(sA, evX1, 0);
        if (t > 0) {
            const h16* ah = p_hfh + (size_t)(t - 1) * BB * 1024;
            const h16* al = p_hfl + (size_t)(t - 1) * BB * 1024;
            // 3 segs x 16 chunks (K=1024) = 48 chunks, z=4 k-split -> 128 CTAs
            gemm_f16<<<dim3(32, 1, 4), 256, SMEM, sA>>>(
                ah, al, ah, p_Whhh, p_Whhh, p_Whhl,
                nullptr, nullptr, p_part, BB, G4, 12, GTZ, 0, 16, 1024, 1024);
        }
        lstm_ew<<<(BB * HH) / 256, 256, 0, sA>>>(t, t > 0 ? 4 : 0);
    }

    // projection: single launch after recurrence (rows via rowmap, single fp16 pass)
    gemm_f16<<<dim3((VV + 127) / 128, (N + 127) / 128, 1), 256, SMEM, sA>>>(
        p_hfh, p_hfh, p_hfh, p_Wlf, p_Wlf, p_Wlf,
        p_map, b_lin, out, N, VV, 16, 0, 0, 16, 1024, 1024);

    // join
    cudaEventRecord(evJA, sA);
    cudaEventRecord(evJB, sB);
    cudaStreamWaitEvent(0, evJA, 0);
    cudaStreamWaitEvent(0, evJB, 0);
}